// round 6
// baseline (speedup 1.0000x reference)
#include <cuda_runtime.h>
#include <cuda_bf16.h>
#include <cstdint>
#include <math.h>

#define Bv 64
#define Tv 512
#define Iv 1024
#define Hv 1024
#define Gv 4096   // 4*H

// ---------------------------------------------------------------------------
// Static device scratch
// ---------------------------------------------------------------------------
__device__ float g_Gx[(size_t)Tv * Bv * Gv];              // 512MB [T][B][4H]
__device__ __nv_bfloat16 g_x_hi[(size_t)Bv * Tv * Iv];    // 64MB
__device__ __nv_bfloat16 g_x_lo[(size_t)Bv * Tv * Iv];    // 64MB
__device__ __nv_bfloat16 g_Wih_hi[(size_t)Gv * Iv];       // 8MB
__device__ __nv_bfloat16 g_Wih_lo[(size_t)Gv * Iv];
__device__ __nv_bfloat16 g_Whh_hi[(size_t)Gv * Hv];       // 8MB
__device__ __nv_bfloat16 g_Whh_lo[(size_t)Gv * Hv];
__device__ __nv_bfloat16 g_h_hi[2][Bv * Hv];
__device__ __nv_bfloat16 g_h_lo[2][Bv * Hv];
__device__ float g_c[Bv * Hv];
__device__ unsigned int g_ready[8];   // per-128-col slab arrival counters

// ---------------------------------------------------------------------------
// Helpers
// ---------------------------------------------------------------------------
__device__ __forceinline__ uint32_t smem_u32(const void* p) {
    uint32_t a;
    asm("{ .reg .u64 t; cvta.to.shared.u64 t, %1; cvt.u32.u64 %0, t; }"
        : "=r"(a) : "l"(p));
    return a;
}

#define SWZ128(o) ((o) ^ (((o) >> 3) & 0x70))

__device__ __forceinline__ void cp16(uint32_t dst, const void* src) {
    asm volatile("cp.async.cg.shared.global [%0], [%1], 16;" :: "r"(dst), "l"(src));
}
#define CP_COMMIT() asm volatile("cp.async.commit_group;" ::: "memory")
#define CP_WAIT(n)  asm volatile("cp.async.wait_group %0;" :: "n"(n) : "memory")

__device__ __forceinline__ void ldsm4(uint32_t* r, uint32_t addr) {
    asm volatile("ldmatrix.sync.aligned.m8n8.x4.shared.b16 {%0,%1,%2,%3}, [%4];"
        : "=r"(r[0]), "=r"(r[1]), "=r"(r[2]), "=r"(r[3]) : "r"(addr));
}

__device__ __forceinline__ void mma16816(float* d, const uint32_t* a,
                                         uint32_t b0, uint32_t b1) {
    asm volatile(
        "mma.sync.aligned.m16n8k16.row.col.f32.bf16.bf16.f32 "
        "{%0,%1,%2,%3}, {%4,%5,%6,%7}, {%8,%9}, {%0,%1,%2,%3};"
        : "+f"(d[0]), "+f"(d[1]), "+f"(d[2]), "+f"(d[3])
        : "r"(a[0]), "r"(a[1]), "r"(a[2]), "r"(a[3]), "r"(b0), "r"(b1));
}

__device__ __forceinline__ float sigm(float x) {
    return 1.0f / (1.0f + __expf(-x));
}
__device__ __forceinline__ float tanh_fast(float x) {
    float cx = fminf(fmaxf(x, -10.0f), 10.0f);
    float e = __expf(2.0f * cx);
    return (e - 1.0f) / (e + 1.0f);
}

// Spin until g_ready[cidx] >= target (lane0 polls, warp fans out).
__device__ __forceinline__ void wait_ready(int cidx, unsigned int target) {
    if ((threadIdx.x & 31) == 0) {
        unsigned int cur;
        do {
            asm volatile("ld.acquire.gpu.u32 %0, [%1];"
                         : "=r"(cur) : "l"(&g_ready[cidx]) : "memory");
            if (cur >= target) break;
            asm volatile("nanosleep.u32 32;");
        } while (true);
    }
    __syncwarp();
}

// ---------------------------------------------------------------------------
// Warp-level 3-pass split-bf16 MMA over one K-chunk of 64 (proven R4/R5).
// ---------------------------------------------------------------------------
template <int NT>
__device__ __forceinline__ void warp_mma_chunk(
    uint32_t aHi, uint32_t aLo, uint32_t bHi, uint32_t bLo,
    int mrow, int nbase, int lane, float acc[][4])
{
    const int arowoff = (lane & 7) + ((lane >> 3) & 1) * 8;
    const int nrowoff = (lane & 7) + ((lane >> 4) & 1) * 8;
    #pragma unroll
    for (int kk = 0; kk < 4; kk++) {
        uint32_t ah[2][4], al[2][4], bh[NT][4], bl[NT][4];
        const int akoff = kk * 32 + (lane >> 4) * 16;
        const int bkoff = kk * 32 + ((lane >> 3) & 1) * 16;
        #pragma unroll
        for (int m = 0; m < 2; m++) {
            uint32_t off = SWZ128((uint32_t)((mrow + m * 16 + arowoff) * 128 + akoff));
            ldsm4(ah[m], aHi + off);
            ldsm4(al[m], aLo + off);
        }
        #pragma unroll
        for (int jb = 0; jb < NT; jb++) {
            uint32_t off = SWZ128((uint32_t)((nbase + jb * 16 + nrowoff) * 128 + bkoff));
            ldsm4(bh[jb], bHi + off);
            ldsm4(bl[jb], bLo + off);
        }
        #pragma unroll
        for (int jb = 0; jb < NT; jb++)
            #pragma unroll
            for (int m = 0; m < 2; m++) {
                mma16816(acc[m * 2 * NT + jb * 2],     ah[m], bh[jb][0], bh[jb][1]);
                mma16816(acc[m * 2 * NT + jb * 2 + 1], ah[m], bh[jb][2], bh[jb][3]);
            }
        #pragma unroll
        for (int jb = 0; jb < NT; jb++)
            #pragma unroll
            for (int m = 0; m < 2; m++) {
                mma16816(acc[m * 2 * NT + jb * 2],     al[m], bh[jb][0], bh[jb][1]);
                mma16816(acc[m * 2 * NT + jb * 2 + 1], al[m], bh[jb][2], bh[jb][3]);
            }
        #pragma unroll
        for (int jb = 0; jb < NT; jb++)
            #pragma unroll
            for (int m = 0; m < 2; m++) {
                mma16816(acc[m * 2 * NT + jb * 2],     ah[m], bl[jb][0], bl[jb][1]);
                mma16816(acc[m * 2 * NT + jb * 2 + 1], ah[m], bl[jb][2], bl[jb][3]);
            }
    }
}

// ---------------------------------------------------------------------------
// Prep kernels (device symbols bound in device code — R3 lesson).
// ---------------------------------------------------------------------------
__global__ void split_kernel(const float* __restrict__ src, int which, size_t n) {
    __nv_bfloat16* hi;
    __nv_bfloat16* lo;
    if (which == 0)      { hi = g_x_hi;   lo = g_x_lo;   }
    else if (which == 1) { hi = g_Wih_hi; lo = g_Wih_lo; }
    else                 { hi = g_Whh_hi; lo = g_Whh_lo; }
    size_t stride = (size_t)gridDim.x * blockDim.x;
    for (size_t i = (size_t)blockIdx.x * blockDim.x + threadIdx.x; i < n; i += stride) {
        float v = src[i];
        __nv_bfloat16 h = __float2bfloat16(v);
        hi[i] = h;
        lo[i] = __float2bfloat16(v - __bfloat162float(h));
    }
}

__global__ void init_state_kernel() {
    int i = blockIdx.x * blockDim.x + threadIdx.x;
    if (i < 8) g_ready[i] = 0u;
    if (i < Bv * Hv) {
        g_h_hi[0][i] = __float2bfloat16(0.0f);
        g_h_lo[0][i] = __float2bfloat16(0.0f);
        g_c[i] = 0.0f;
    }
}

// ---------------------------------------------------------------------------
// Input GEMM (HMMA, unchanged from R4/R5 pass)
// ---------------------------------------------------------------------------
#define G_STAGE 65536
#define G_SMEM  (2 * G_STAGE)

__device__ __forceinline__ void gemm_load(uint32_t sb, int s, int k0,
                                          int m0, int n0, int tid) {
    uint32_t base = sb + (uint32_t)s * G_STAGE;
    #pragma unroll
    for (int r = 0; r < 8; r++) {
        int idx = tid + r * 256;
        int hf = idx >> 10, rem = idx & 1023;
        int row = rem >> 3, c = rem & 7;
        const __nv_bfloat16* src = (hf ? g_x_lo : g_x_hi)
                                   + (size_t)(m0 + row) * Iv + k0 + c * 8;
        cp16(base + hf * 16384 + SWZ128((uint32_t)(row * 128 + c * 16)), src);
    }
    #pragma unroll
    for (int r = 0; r < 8; r++) {
        int idx = tid + r * 256;
        int hf = idx >> 10, rem = idx & 1023;
        int row = rem >> 3, c = rem & 7;
        const __nv_bfloat16* src = (hf ? g_Wih_lo : g_Wih_hi)
                                   + (size_t)(n0 + row) * Iv + k0 + c * 8;
        cp16(base + 32768 + hf * 16384 + SWZ128((uint32_t)(row * 128 + c * 16)), src);
    }
}

__global__ void __launch_bounds__(256, 1) gemm_in_mma(const float* __restrict__ bias)
{
    extern __shared__ char smem[];
    uint32_t sb = smem_u32(smem);
    const int tid = threadIdx.x, lane = tid & 31, wid = tid >> 5;
    const int m0 = blockIdx.y * 128, n0 = blockIdx.x * 128;

    float acc[16][4];
    #pragma unroll
    for (int i = 0; i < 16; i++)
        #pragma unroll
        for (int j = 0; j < 4; j++) acc[i][j] = 0.0f;

    gemm_load(sb, 0, 0, m0, n0, tid);
    CP_COMMIT();

    const int mrow = (wid & 3) * 32, nbase = (wid >> 2) * 64;
    for (int it = 0; it < 16; it++) {
        const int s = it & 1;
        if (it + 1 < 16) {
            gemm_load(sb, (it + 1) & 1, (it + 1) * 64, m0, n0, tid);
            CP_COMMIT();
            CP_WAIT(1);
        } else {
            CP_WAIT(0);
        }
        __syncthreads();
        uint32_t base = sb + (uint32_t)s * G_STAGE;
        warp_mma_chunk<4>(base, base + 16384, base + 32768, base + 49152,
                          mrow, nbase, lane, acc);
        __syncthreads();
    }

    #pragma unroll
    for (int m = 0; m < 2; m++)
        #pragma unroll
        for (int j = 0; j < 8; j++) {
            float* a = acc[m * 8 + j];
            int gr = m0 + (wid & 3) * 32 + m * 16 + (lane >> 2);
            int n  = n0 + (wid >> 2) * 64 + j * 8 + 2 * (lane & 3);
            float b0 = bias[n], b1 = bias[n + 1];
            int bi0 = gr >> 9, tt0 = gr & 511;
            float* o0 = g_Gx + ((size_t)tt0 * Bv + bi0) * Gv + n;
            o0[0] = a[0] + b0; o0[1] = a[1] + b1;
            int gr2 = gr + 8, bi2 = gr2 >> 9, tt2 = gr2 & 511;
            float* o2 = g_Gx + ((size_t)tt2 * Bv + bi2) * Gv + n;
            o2[0] = a[2] + b0; o2[1] = a[3] + b1;
        }
}

// ---------------------------------------------------------------------------
// Persistent LSTM recurrence. 128 CTAs x 256 threads, 1 CTA/SM.
// CTA owns 8 hidden cols (32 gate rows). Whh hi+lo (128KB) SMEM-resident.
// h streamed per step: 16 K-chunks of 64, 3-stage cp.async pipeline, ONE
// __syncthreads per chunk. Per-slab ready counters replace the grid barrier.
// ---------------------------------------------------------------------------
#define WS_HI 0
#define WS_LO 65536
#define AB    131072                      /* 3 stages x (hi 8KB + lo 8KB) */
#define GS0   180224                      /* 64 x 33 fp32 = 8448 */
#define GS1   188672
#define P_SMEM 197120

__device__ __forceinline__ void persist_loadA(uint32_t sb, int st, int k0,
                                              const __nv_bfloat16* __restrict__ hHi,
                                              const __nv_bfloat16* __restrict__ hLo,
                                              int tid) {
    uint32_t base = sb + AB + (uint32_t)st * 16384;
    #pragma unroll
    for (int r = 0; r < 4; r++) {          // 1024 cp16 = 16KB
        int idx = tid + r * 256;
        int hf = idx >> 9, rem = idx & 511;
        int row = rem >> 3, c = rem & 7;   // row = batch 0..63
        const __nv_bfloat16* src = (hf ? hLo : hHi) + (size_t)row * Hv + k0 + c * 8;
        cp16(base + hf * 8192 + SWZ128((uint32_t)(row * 128 + c * 16)), src);
    }
}

__global__ void __launch_bounds__(256, 1) lstm_persistent(float* __restrict__ dout)
{
    extern __shared__ char smem[];
    uint32_t sb = smem_u32(smem);
    const int tid = threadIdx.x, lane = tid & 31, wid = tid >> 5;
    const int j0 = blockIdx.x * 8;
    const int my_slab = blockIdx.x >> 4;       // 16 CTAs per 128-col slab
    const int par = wid >> 2;                  // chunk parity this warp computes
    const int mrow = (wid & 1) * 32;
    const int nbase = ((wid >> 1) & 1) * 16;

    // ---- Preload Whh hi+lo tile (resident all 512 steps)
    #pragma unroll
    for (int r = 0; r < 32; r++) {             // 8192 cp16 = 128KB
        int idx = tid + r * 256;
        int hf = idx >> 12, rem = idx & 4095;
        int chunk = rem >> 8, within = rem & 255;
        int row = within >> 3, c = within & 7;
        int gate = row >> 3, jc = row & 7;
        const __nv_bfloat16* src = (hf ? g_Whh_lo : g_Whh_hi)
            + (size_t)(gate * Hv + j0 + jc) * Hv + chunk * 64 + c * 8;
        cp16(sb + (hf ? WS_LO : WS_HI) + chunk * 4096
                + SWZ128((uint32_t)(row * 128 + c * 16)), src);
    }
    CP_COMMIT();
    CP_WAIT(0);
    __syncthreads();

    float* Gs0 = (float*)(smem + GS0);
    float* Gs1 = (float*)(smem + GS1);

    for (int t = 0; t < Tv; t++) {
        const unsigned int tgt = 16u * (unsigned int)t;
        const __nv_bfloat16* hHi = g_h_hi[t & 1];
        const __nv_bfloat16* hLo = g_h_lo[t & 1];
        __nv_bfloat16* hHiN = g_h_hi[(t + 1) & 1];
        __nv_bfloat16* hLoN = g_h_lo[(t + 1) & 1];

        float acc[4][4];
        #pragma unroll
        for (int i = 0; i < 4; i++)
            #pragma unroll
            for (int j = 0; j < 4; j++) acc[i][j] = 0.0f;

        // prologue: chunks 0,1 (slab counter 0 covers both)
        wait_ready(0, tgt);
        persist_loadA(sb, 0, 0,  hHi, hLo, tid);
        CP_COMMIT();
        persist_loadA(sb, 1, 64, hHi, hLo, tid);
        CP_COMMIT();

        for (int it = 0; it < 16; it++) {
            if (it == 15) { CP_WAIT(0); } else { CP_WAIT(1); }
            __syncthreads();
            if ((it & 1) == par) {
                uint32_t aHi = sb + AB + (uint32_t)(it % 3) * 16384;
                warp_mma_chunk<1>(aHi, aHi + 8192,
                                  sb + WS_HI + (uint32_t)it * 4096,
                                  sb + WS_LO + (uint32_t)it * 4096,
                                  mrow, nbase, lane, acc);
            }
            if (it + 2 < 16) {
                if (((it + 2) & 1) == 0) wait_ready((it + 2) >> 1, tgt);
                persist_loadA(sb, (it + 2) % 3, (it + 2) * 64, hHi, hLo, tid);
                CP_COMMIT();
            }
        }

        // Stage partial gates (per k-parity buffer)
        float* Gs = par ? Gs1 : Gs0;
        #pragma unroll
        for (int m = 0; m < 2; m++)
            #pragma unroll
            for (int p = 0; p < 2; p++) {
                float* a = acc[m * 2 + p];
                int r0 = mrow + m * 16 + (lane >> 2);
                int cc = nbase + p * 8 + 2 * (lane & 3);
                Gs[r0 * 33 + cc]           = a[0];
                Gs[r0 * 33 + cc + 1]       = a[1];
                Gs[(r0 + 8) * 33 + cc]     = a[2];
                Gs[(r0 + 8) * 33 + cc + 1] = a[3];
            }
        __syncthreads();

        // Fused cell update: 512 cells (64 batch x 8 hidden cols)
        #pragma unroll
        for (int p = 0; p < 2; p++) {
            int cell = tid + p * 256;
            int b = cell >> 3, jc = cell & 7;
            const float* gxr = g_Gx + ((size_t)t * Bv + b) * Gv + j0 + jc;
            float gi = Gs0[b * 33 + jc]      + Gs1[b * 33 + jc]      + gxr[0];
            float gf = Gs0[b * 33 + 8 + jc]  + Gs1[b * 33 + 8 + jc]  + gxr[1024];
            float gg = Gs0[b * 33 + 16 + jc] + Gs1[b * 33 + 16 + jc] + gxr[2048];
            float go = Gs0[b * 33 + 24 + jc] + Gs1[b * 33 + 24 + jc] + gxr[3072];

            int hidx = b * Hv + j0 + jc;
            float c_old = g_c[hidx];
            float cn = sigm(gf) * c_old + sigm(gi) * tanh_fast(gg);
            float hn = sigm(go) * tanh_fast(cn);
            g_c[hidx] = cn;

            __nv_bfloat16 hi = __float2bfloat16(hn);
            hHiN[hidx] = hi;
            hLoN[hidx] = __float2bfloat16(hn - __bfloat162float(hi));

            dout[(size_t)b * Tv * Hv + (size_t)t * Hv + j0 + jc] = hn;
            if (t == Tv - 1) {
                size_t obase = (size_t)Bv * Tv * Hv;
                dout[obase + hidx] = hn;                    // h_T
                dout[obase + (size_t)Bv * Hv + hidx] = cn;  // c_T
            }
        }

        // ---- arrive: this CTA's slab columns for step t are published
        __syncthreads();
        if (tid == 0) {
            unsigned int ignored;
            asm volatile("atom.add.release.gpu.u32 %0, [%1], 1;"
                         : "=r"(ignored) : "l"(&g_ready[my_slab]) : "memory");
        }
    }
}

// ---------------------------------------------------------------------------
// Launch
// ---------------------------------------------------------------------------
extern "C" void kernel_launch(void* const* d_in, const int* in_sizes, int n_in,
                              void* d_out, int out_size)
{
    const float* x    = (const float*)d_in[0];  // [B, T, I]
    const float* Wih  = (const float*)d_in[1];  // [4H, I]
    const float* Whh  = (const float*)d_in[2];  // [4H, H]
    const float* bias = (const float*)d_in[3];  // [4H]
    float* out = (float*)d_out;
    (void)in_sizes; (void)n_in; (void)out_size;

    cudaFuncSetAttribute(gemm_in_mma,     cudaFuncAttributeMaxDynamicSharedMemorySize, G_SMEM);
    cudaFuncSetAttribute(lstm_persistent, cudaFuncAttributeMaxDynamicSharedMemorySize, P_SMEM);

    split_kernel<<<8192, 256>>>(x,   0, (size_t)Bv * Tv * Iv);
    split_kernel<<<4096, 256>>>(Wih, 1, (size_t)Gv * Iv);
    split_kernel<<<4096, 256>>>(Whh, 2, (size_t)Gv * Hv);
    init_state_kernel<<<(Bv * Hv + 255) / 256, 256>>>();

    dim3 ggrid(Gv / 128, (Bv * Tv) / 128);   // (32, 256)
    gemm_in_mma<<<ggrid, 256, G_SMEM>>>(bias);

    lstm_persistent<<<128, 256, P_SMEM>>>(out);
}

// round 7
// speedup vs baseline: 1.1559x; 1.1559x over previous
#include <cuda_runtime.h>
#include <cuda_bf16.h>
#include <cstdint>
#include <math.h>

#define Bv 64
#define Tv 512
#define Iv 1024
#define Hv 1024
#define Gv 4096   // 4*H

// ---------------------------------------------------------------------------
// Static device scratch
// ---------------------------------------------------------------------------
__device__ float g_Gx[(size_t)Tv * Bv * Gv];              // 512MB [T][B][4H]
__device__ __nv_bfloat16 g_x_hi[(size_t)Bv * Tv * Iv];    // 64MB
__device__ __nv_bfloat16 g_x_lo[(size_t)Bv * Tv * Iv];    // 64MB
__device__ __nv_bfloat16 g_Wih_hi[(size_t)Gv * Iv];       // 8MB
__device__ __nv_bfloat16 g_Wih_lo[(size_t)Gv * Iv];
__device__ __nv_bfloat16 g_Whh_hi[(size_t)Gv * Hv];       // 8MB
__device__ __nv_bfloat16 g_Whh_lo[(size_t)Gv * Hv];
__device__ __nv_bfloat16 g_h_hi[2][Bv * Hv];
__device__ __nv_bfloat16 g_h_lo[2][Bv * Hv];
__device__ float g_c[Bv * Hv];
__device__ unsigned int g_bar;

// ---------------------------------------------------------------------------
// Helpers
// ---------------------------------------------------------------------------
__device__ __forceinline__ uint32_t smem_u32(const void* p) {
    uint32_t a;
    asm("{ .reg .u64 t; cvta.to.shared.u64 t, %1; cvt.u32.u64 %0, t; }"
        : "=r"(a) : "l"(p));
    return a;
}

#define SWZ128(o) ((o) ^ (((o) >> 3) & 0x70))

__device__ __forceinline__ void cp16(uint32_t dst, const void* src) {
    asm volatile("cp.async.cg.shared.global [%0], [%1], 16;" :: "r"(dst), "l"(src));
}
#define CP_COMMIT() asm volatile("cp.async.commit_group;" ::: "memory")
#define CP_WAIT(n)  asm volatile("cp.async.wait_group %0;" :: "n"(n) : "memory")

__device__ __forceinline__ void ldsm4(uint32_t* r, uint32_t addr) {
    asm volatile("ldmatrix.sync.aligned.m8n8.x4.shared.b16 {%0,%1,%2,%3}, [%4];"
        : "=r"(r[0]), "=r"(r[1]), "=r"(r[2]), "=r"(r[3]) : "r"(addr));
}

__device__ __forceinline__ void mma16816(float* d, const uint32_t* a,
                                         uint32_t b0, uint32_t b1) {
    asm volatile(
        "mma.sync.aligned.m16n8k16.row.col.f32.bf16.bf16.f32 "
        "{%0,%1,%2,%3}, {%4,%5,%6,%7}, {%8,%9}, {%0,%1,%2,%3};"
        : "+f"(d[0]), "+f"(d[1]), "+f"(d[2]), "+f"(d[3])
        : "r"(a[0]), "r"(a[1]), "r"(a[2]), "r"(a[3]), "r"(b0), "r"(b1));
}

__device__ __forceinline__ float sigm(float x) {
    return 1.0f / (1.0f + __expf(-x));
}
__device__ __forceinline__ float tanh_fast(float x) {
    float cx = fminf(fmaxf(x, -10.0f), 10.0f);
    float e = __expf(2.0f * cx);
    return (e - 1.0f) / (e + 1.0f);
}

// ---------------------------------------------------------------------------
// Warp-level 3-pass split-bf16 MMA over one K-chunk of 64 (proven R4/R5).
// ---------------------------------------------------------------------------
template <int NT>
__device__ __forceinline__ void warp_mma_chunk(
    uint32_t aHi, uint32_t aLo, uint32_t bHi, uint32_t bLo,
    int mrow, int nbase, int lane, float acc[][4])
{
    const int arowoff = (lane & 7) + ((lane >> 3) & 1) * 8;
    const int nrowoff = (lane & 7) + ((lane >> 4) & 1) * 8;
    #pragma unroll
    for (int kk = 0; kk < 4; kk++) {
        uint32_t ah[2][4], al[2][4], bh[NT][4], bl[NT][4];
        const int akoff = kk * 32 + (lane >> 4) * 16;
        const int bkoff = kk * 32 + ((lane >> 3) & 1) * 16;
        #pragma unroll
        for (int m = 0; m < 2; m++) {
            uint32_t off = SWZ128((uint32_t)((mrow + m * 16 + arowoff) * 128 + akoff));
            ldsm4(ah[m], aHi + off);
            ldsm4(al[m], aLo + off);
        }
        #pragma unroll
        for (int jb = 0; jb < NT; jb++) {
            uint32_t off = SWZ128((uint32_t)((nbase + jb * 16 + nrowoff) * 128 + bkoff));
            ldsm4(bh[jb], bHi + off);
            ldsm4(bl[jb], bLo + off);
        }
        #pragma unroll
        for (int jb = 0; jb < NT; jb++)
            #pragma unroll
            for (int m = 0; m < 2; m++) {
                mma16816(acc[m * 2 * NT + jb * 2],     ah[m], bh[jb][0], bh[jb][1]);
                mma16816(acc[m * 2 * NT + jb * 2 + 1], ah[m], bh[jb][2], bh[jb][3]);
            }
        #pragma unroll
        for (int jb = 0; jb < NT; jb++)
            #pragma unroll
            for (int m = 0; m < 2; m++) {
                mma16816(acc[m * 2 * NT + jb * 2],     al[m], bh[jb][0], bh[jb][1]);
                mma16816(acc[m * 2 * NT + jb * 2 + 1], al[m], bh[jb][2], bh[jb][3]);
            }
        #pragma unroll
        for (int jb = 0; jb < NT; jb++)
            #pragma unroll
            for (int m = 0; m < 2; m++) {
                mma16816(acc[m * 2 * NT + jb * 2],     ah[m], bl[jb][0], bl[jb][1]);
                mma16816(acc[m * 2 * NT + jb * 2 + 1], ah[m], bl[jb][2], bl[jb][3]);
            }
    }
}

// ---------------------------------------------------------------------------
// Prep kernels (device symbols bound in device code — R3 lesson).
// ---------------------------------------------------------------------------
__global__ void split_kernel(const float* __restrict__ src, int which, size_t n) {
    __nv_bfloat16* hi;
    __nv_bfloat16* lo;
    if (which == 0)      { hi = g_x_hi;   lo = g_x_lo;   }
    else if (which == 1) { hi = g_Wih_hi; lo = g_Wih_lo; }
    else                 { hi = g_Whh_hi; lo = g_Whh_lo; }
    size_t stride = (size_t)gridDim.x * blockDim.x;
    for (size_t i = (size_t)blockIdx.x * blockDim.x + threadIdx.x; i < n; i += stride) {
        float v = src[i];
        __nv_bfloat16 h = __float2bfloat16(v);
        hi[i] = h;
        lo[i] = __float2bfloat16(v - __bfloat162float(h));
    }
}

__global__ void init_state_kernel() {
    int i = blockIdx.x * blockDim.x + threadIdx.x;
    if (i == 0) g_bar = 0u;
    if (i < Bv * Hv) {
        g_h_hi[0][i] = __float2bfloat16(0.0f);
        g_h_lo[0][i] = __float2bfloat16(0.0f);
        g_c[i] = 0.0f;
    }
}

// ---------------------------------------------------------------------------
// Input GEMM (HMMA, unchanged from R4/R5 pass)
// ---------------------------------------------------------------------------
#define G_STAGE 65536
#define G_SMEM  (2 * G_STAGE)

__device__ __forceinline__ void gemm_load(uint32_t sb, int s, int k0,
                                          int m0, int n0, int tid) {
    uint32_t base = sb + (uint32_t)s * G_STAGE;
    #pragma unroll
    for (int r = 0; r < 8; r++) {
        int idx = tid + r * 256;
        int hf = idx >> 10, rem = idx & 1023;
        int row = rem >> 3, c = rem & 7;
        const __nv_bfloat16* src = (hf ? g_x_lo : g_x_hi)
                                   + (size_t)(m0 + row) * Iv + k0 + c * 8;
        cp16(base + hf * 16384 + SWZ128((uint32_t)(row * 128 + c * 16)), src);
    }
    #pragma unroll
    for (int r = 0; r < 8; r++) {
        int idx = tid + r * 256;
        int hf = idx >> 10, rem = idx & 1023;
        int row = rem >> 3, c = rem & 7;
        const __nv_bfloat16* src = (hf ? g_Wih_lo : g_Wih_hi)
                                   + (size_t)(n0 + row) * Iv + k0 + c * 8;
        cp16(base + 32768 + hf * 16384 + SWZ128((uint32_t)(row * 128 + c * 16)), src);
    }
}

__global__ void __launch_bounds__(256, 1) gemm_in_mma(const float* __restrict__ bias)
{
    extern __shared__ char smem[];
    uint32_t sb = smem_u32(smem);
    const int tid = threadIdx.x, lane = tid & 31, wid = tid >> 5;
    const int m0 = blockIdx.y * 128, n0 = blockIdx.x * 128;

    float acc[16][4];
    #pragma unroll
    for (int i = 0; i < 16; i++)
        #pragma unroll
        for (int j = 0; j < 4; j++) acc[i][j] = 0.0f;

    gemm_load(sb, 0, 0, m0, n0, tid);
    CP_COMMIT();

    const int mrow = (wid & 3) * 32, nbase = (wid >> 2) * 64;
    for (int it = 0; it < 16; it++) {
        const int s = it & 1;
        if (it + 1 < 16) {
            gemm_load(sb, (it + 1) & 1, (it + 1) * 64, m0, n0, tid);
            CP_COMMIT();
            CP_WAIT(1);
        } else {
            CP_WAIT(0);
        }
        __syncthreads();
        uint32_t base = sb + (uint32_t)s * G_STAGE;
        warp_mma_chunk<4>(base, base + 16384, base + 32768, base + 49152,
                          mrow, nbase, lane, acc);
        __syncthreads();
    }

    #pragma unroll
    for (int m = 0; m < 2; m++)
        #pragma unroll
        for (int j = 0; j < 8; j++) {
            float* a = acc[m * 8 + j];
            int gr = m0 + (wid & 3) * 32 + m * 16 + (lane >> 2);
            int n  = n0 + (wid >> 2) * 64 + j * 8 + 2 * (lane & 3);
            float b0 = bias[n], b1 = bias[n + 1];
            int bi0 = gr >> 9, tt0 = gr & 511;
            float* o0 = g_Gx + ((size_t)tt0 * Bv + bi0) * Gv + n;
            o0[0] = a[0] + b0; o0[1] = a[1] + b1;
            int gr2 = gr + 8, bi2 = gr2 >> 9, tt2 = gr2 & 511;
            float* o2 = g_Gx + ((size_t)tt2 * Bv + bi2) * Gv + n;
            o2[0] = a[2] + b0; o2[1] = a[3] + b1;
        }
}

// ---------------------------------------------------------------------------
// Persistent LSTM recurrence. 128 CTAs x 256 threads, 1 CTA/SM.
// CTA owns 8 hidden cols (32 gate rows). Whh hi+lo (128KB) SMEM-resident.
// Per step: 16 K-chunks of 64, 3-stage cp.async pipeline, ONE __syncthreads
// per chunk; Gx gate slice prefetched to SMEM with chunk 0; single global
// release/acquire barrier per step (R5 scheme — R6's per-slab waits regressed).
// ---------------------------------------------------------------------------
#define WS_HI 0
#define WS_LO 65536
#define AB    131072                      /* 3 stages x (hi 8KB + lo 8KB) */
#define GXS   180224                      /* 64 rows x 144B = 9216 */
#define GS0   189440                      /* 64 x 33 fp32 = 8448 */
#define GS1   197888
#define P_SMEM 206336

__device__ __forceinline__ void persist_loadA(uint32_t sb, int st, int k0,
                                              const __nv_bfloat16* __restrict__ hHi,
                                              const __nv_bfloat16* __restrict__ hLo,
                                              int tid) {
    uint32_t base = sb + AB + (uint32_t)st * 16384;
    #pragma unroll
    for (int r = 0; r < 4; r++) {          // 1024 cp16 = 16KB
        int idx = tid + r * 256;
        int hf = idx >> 9, rem = idx & 511;
        int row = rem >> 3, c = rem & 7;   // row = batch 0..63
        const __nv_bfloat16* src = (hf ? hLo : hHi) + (size_t)row * Hv + k0 + c * 8;
        cp16(base + hf * 8192 + SWZ128((uint32_t)(row * 128 + c * 16)), src);
    }
}

__global__ void __launch_bounds__(256, 1) lstm_persistent(float* __restrict__ dout)
{
    extern __shared__ char smem[];
    uint32_t sb = smem_u32(smem);
    const int tid = threadIdx.x, lane = tid & 31, wid = tid >> 5;
    const int j0 = blockIdx.x * 8;
    const int par = wid >> 2;                  // chunk parity this warp computes
    const int mrow = (wid & 1) * 32;
    const int nbase = ((wid >> 1) & 1) * 16;

    // ---- Preload Whh hi+lo tile (resident all 512 steps)
    #pragma unroll
    for (int r = 0; r < 32; r++) {             // 8192 cp16 = 128KB
        int idx = tid + r * 256;
        int hf = idx >> 12, rem = idx & 4095;
        int chunk = rem >> 8, within = rem & 255;
        int row = within >> 3, c = within & 7;
        int gate = row >> 3, jc = row & 7;
        const __nv_bfloat16* src = (hf ? g_Whh_lo : g_Whh_hi)
            + (size_t)(gate * Hv + j0 + jc) * Hv + chunk * 64 + c * 8;
        cp16(sb + (hf ? WS_LO : WS_HI) + chunk * 4096
                + SWZ128((uint32_t)(row * 128 + c * 16)), src);
    }
    CP_COMMIT();
    CP_WAIT(0);
    __syncthreads();

    float* Gs0 = (float*)(smem + GS0);
    float* Gs1 = (float*)(smem + GS1);
    float* gxs = (float*)(smem + GXS);

    for (int t = 0; t < Tv; t++) {
        const __nv_bfloat16* hHi = g_h_hi[t & 1];
        const __nv_bfloat16* hLo = g_h_lo[t & 1];
        __nv_bfloat16* hHiN = g_h_hi[(t + 1) & 1];
        __nv_bfloat16* hLoN = g_h_lo[(t + 1) & 1];

        float acc[4][4];
        #pragma unroll
        for (int i = 0; i < 4; i++)
            #pragma unroll
            for (int j = 0; j < 4; j++) acc[i][j] = 0.0f;

        // prologue: chunk 0 (+ Gx gate-slice prefetch in the same group), chunk 1
        persist_loadA(sb, 0, 0, hHi, hLo, tid);
        {
            const float* gxbase = g_Gx + ((size_t)t * Bv) * Gv + j0;
            #pragma unroll
            for (int r = 0; r < 2; r++) {       // 512 cp16 = 8KB (row stride 144B)
                int idx = tid + r * 256;
                int b = idx >> 3;
                int gate = (idx >> 1) & 3, hf = idx & 1;
                cp16(sb + GXS + (uint32_t)(b * 144 + gate * 32 + hf * 16),
                     gxbase + (size_t)b * Gv + gate * Hv + hf * 4);
            }
        }
        CP_COMMIT();
        persist_loadA(sb, 1, 64, hHi, hLo, tid);
        CP_COMMIT();

        for (int it = 0; it < 16; it++) {
            if (it == 15) { CP_WAIT(0); } else { CP_WAIT(1); }
            __syncthreads();
            if ((it & 1) == par) {
                uint32_t aHi = sb + AB + (uint32_t)(it % 3) * 16384;
                warp_mma_chunk<1>(aHi, aHi + 8192,
                                  sb + WS_HI + (uint32_t)it * 4096,
                                  sb + WS_LO + (uint32_t)it * 4096,
                                  mrow, nbase, lane, acc);
            }
            if (it + 2 < 16) {
                persist_loadA(sb, (it + 2) % 3, (it + 2) * 64, hHi, hLo, tid);
                CP_COMMIT();
            }
        }

        // Stage partial gates (per k-parity buffer)
        float* Gs = par ? Gs1 : Gs0;
        #pragma unroll
        for (int m = 0; m < 2; m++)
            #pragma unroll
            for (int p = 0; p < 2; p++) {
                float* a = acc[m * 2 + p];
                int r0 = mrow + m * 16 + (lane >> 2);
                int cc = nbase + p * 8 + 2 * (lane & 3);
                Gs[r0 * 33 + cc]           = a[0];
                Gs[r0 * 33 + cc + 1]       = a[1];
                Gs[(r0 + 8) * 33 + cc]     = a[2];
                Gs[(r0 + 8) * 33 + cc + 1] = a[3];
            }
        __syncthreads();

        // Fused cell update: 512 cells (64 batch x 8 hidden cols), Gx from SMEM
        #pragma unroll
        for (int p = 0; p < 2; p++) {
            int cell = tid + p * 256;
            int b = cell >> 3, jc = cell & 7;
            const float* gx = gxs + b * 36;
            float gi = Gs0[b * 33 + jc]      + Gs1[b * 33 + jc]      + gx[jc];
            float gf = Gs0[b * 33 + 8 + jc]  + Gs1[b * 33 + 8 + jc]  + gx[8 + jc];
            float gg = Gs0[b * 33 + 16 + jc] + Gs1[b * 33 + 16 + jc] + gx[16 + jc];
            float go = Gs0[b * 33 + 24 + jc] + Gs1[b * 33 + 24 + jc] + gx[24 + jc];

            int hidx = b * Hv + j0 + jc;
            float c_old = g_c[hidx];
            float cn = sigm(gf) * c_old + sigm(gi) * tanh_fast(gg);
            float hn = sigm(go) * tanh_fast(cn);
            g_c[hidx] = cn;

            __nv_bfloat16 hi = __float2bfloat16(hn);
            hHiN[hidx] = hi;
            hLoN[hidx] = __float2bfloat16(hn - __bfloat162float(hi));

            dout[(size_t)b * Tv * Hv + (size_t)t * Hv + j0 + jc] = hn;
            if (t == Tv - 1) {
                size_t obase = (size_t)Bv * Tv * Hv;
                dout[obase + hidx] = hn;                    // h_T
                dout[obase + (size_t)Bv * Hv + hidx] = cn;  // c_T
            }
        }

        // ---- Global barrier (release-arrive by tid0, acquire-spin, fanout)
        __syncthreads();
        if (tid == 0) {
            unsigned int ignored;
            asm volatile("atom.add.release.gpu.u32 %0, [%1], 1;"
                         : "=r"(ignored) : "l"(&g_bar) : "memory");
            unsigned int target = 128u * (unsigned int)(t + 1);
            unsigned int cur;
            do {
                asm volatile("ld.acquire.gpu.u32 %0, [%1];"
                             : "=r"(cur) : "l"(&g_bar) : "memory");
                if (cur >= target) break;
                asm volatile("nanosleep.u32 16;");
            } while (true);
        }
        __syncthreads();
    }
}

// ---------------------------------------------------------------------------
// Launch
// ---------------------------------------------------------------------------
extern "C" void kernel_launch(void* const* d_in, const int* in_sizes, int n_in,
                              void* d_out, int out_size)
{
    const float* x    = (const float*)d_in[0];  // [B, T, I]
    const float* Wih  = (const float*)d_in[1];  // [4H, I]
    const float* Whh  = (const float*)d_in[2];  // [4H, H]
    const float* bias = (const float*)d_in[3];  // [4H]
    float* out = (float*)d_out;
    (void)in_sizes; (void)n_in; (void)out_size;

    cudaFuncSetAttribute(gemm_in_mma,     cudaFuncAttributeMaxDynamicSharedMemorySize, G_SMEM);
    cudaFuncSetAttribute(lstm_persistent, cudaFuncAttributeMaxDynamicSharedMemorySize, P_SMEM);

    split_kernel<<<8192, 256>>>(x,   0, (size_t)Bv * Tv * Iv);
    split_kernel<<<4096, 256>>>(Wih, 1, (size_t)Gv * Iv);
    split_kernel<<<4096, 256>>>(Whh, 2, (size_t)Gv * Hv);
    init_state_kernel<<<(Bv * Hv + 255) / 256, 256>>>();

    dim3 ggrid(Gv / 128, (Bv * Tv) / 128);   // (32, 256)
    gemm_in_mma<<<ggrid, 256, G_SMEM>>>(bias);

    lstm_persistent<<<128, 256, P_SMEM>>>(out);
}

// round 8
// speedup vs baseline: 1.2195x; 1.0550x over previous
#include <cuda_runtime.h>
#include <cuda_bf16.h>
#include <cuda_fp16.h>
#include <cstdint>
#include <math.h>

#define Bv 64
#define Tv 512
#define Iv 1024
#define Hv 1024
#define Gv 4096   // 4*H

// ---------------------------------------------------------------------------
// Static device scratch
// ---------------------------------------------------------------------------
__device__ float g_Gx[(size_t)Tv * Bv * Gv];              // 512MB [T][B][4H]
__device__ __nv_bfloat16 g_x_hi[(size_t)Bv * Tv * Iv];    // 64MB
__device__ __nv_bfloat16 g_x_lo[(size_t)Bv * Tv * Iv];    // 64MB
__device__ __nv_bfloat16 g_Wih_hi[(size_t)Gv * Iv];       // 8MB
__device__ __nv_bfloat16 g_Wih_lo[(size_t)Gv * Iv];
__device__ __half g_Whh_f16[(size_t)Gv * Hv];             // 8MB, single fp16
__device__ __half g_h_hi[2][Bv * Hv];                     // fp16 h split
__device__ __half g_h_lo[2][Bv * Hv];
__device__ float g_c[Bv * Hv];
__device__ unsigned int g_bar;

// ---------------------------------------------------------------------------
// Helpers
// ---------------------------------------------------------------------------
__device__ __forceinline__ uint32_t smem_u32(const void* p) {
    uint32_t a;
    asm("{ .reg .u64 t; cvta.to.shared.u64 t, %1; cvt.u32.u64 %0, t; }"
        : "=r"(a) : "l"(p));
    return a;
}

#define SWZ128(o) ((o) ^ (((o) >> 3) & 0x70))

__device__ __forceinline__ void cp16(uint32_t dst, const void* src) {
    asm volatile("cp.async.cg.shared.global [%0], [%1], 16;" :: "r"(dst), "l"(src));
}
#define CP_COMMIT() asm volatile("cp.async.commit_group;" ::: "memory")
#define CP_WAIT(n)  asm volatile("cp.async.wait_group %0;" :: "n"(n) : "memory")

__device__ __forceinline__ void ldsm4(uint32_t* r, uint32_t addr) {
    asm volatile("ldmatrix.sync.aligned.m8n8.x4.shared.b16 {%0,%1,%2,%3}, [%4];"
        : "=r"(r[0]), "=r"(r[1]), "=r"(r[2]), "=r"(r[3]) : "r"(addr));
}

__device__ __forceinline__ void mma16816(float* d, const uint32_t* a,
                                         uint32_t b0, uint32_t b1) {
    asm volatile(
        "mma.sync.aligned.m16n8k16.row.col.f32.bf16.bf16.f32 "
        "{%0,%1,%2,%3}, {%4,%5,%6,%7}, {%8,%9}, {%0,%1,%2,%3};"
        : "+f"(d[0]), "+f"(d[1]), "+f"(d[2]), "+f"(d[3])
        : "r"(a[0]), "r"(a[1]), "r"(a[2]), "r"(a[3]), "r"(b0), "r"(b1));
}

__device__ __forceinline__ void mma16816h(float* d, const uint32_t* a,
                                          uint32_t b0, uint32_t b1) {
    asm volatile(
        "mma.sync.aligned.m16n8k16.row.col.f32.f16.f16.f32 "
        "{%0,%1,%2,%3}, {%4,%5,%6,%7}, {%8,%9}, {%0,%1,%2,%3};"
        : "+f"(d[0]), "+f"(d[1]), "+f"(d[2]), "+f"(d[3])
        : "r"(a[0]), "r"(a[1]), "r"(a[2]), "r"(a[3]), "r"(b0), "r"(b1));
}

__device__ __forceinline__ float sigm(float x) {
    return 1.0f / (1.0f + __expf(-x));
}
__device__ __forceinline__ float tanh_fast(float x) {
    float cx = fminf(fmaxf(x, -10.0f), 10.0f);
    float e = __expf(2.0f * cx);
    return (e - 1.0f) / (e + 1.0f);
}

// ---------------------------------------------------------------------------
// bf16 3-pass warp MMA over one K-chunk of 64 (input GEMM, proven R4-R7).
// ---------------------------------------------------------------------------
template <int NT>
__device__ __forceinline__ void warp_mma_chunk(
    uint32_t aHi, uint32_t aLo, uint32_t bHi, uint32_t bLo,
    int mrow, int nbase, int lane, float acc[][4])
{
    const int arowoff = (lane & 7) + ((lane >> 3) & 1) * 8;
    const int nrowoff = (lane & 7) + ((lane >> 4) & 1) * 8;
    #pragma unroll
    for (int kk = 0; kk < 4; kk++) {
        uint32_t ah[2][4], al[2][4], bh[NT][4], bl[NT][4];
        const int akoff = kk * 32 + (lane >> 4) * 16;
        const int bkoff = kk * 32 + ((lane >> 3) & 1) * 16;
        #pragma unroll
        for (int m = 0; m < 2; m++) {
            uint32_t off = SWZ128((uint32_t)((mrow + m * 16 + arowoff) * 128 + akoff));
            ldsm4(ah[m], aHi + off);
            ldsm4(al[m], aLo + off);
        }
        #pragma unroll
        for (int jb = 0; jb < NT; jb++) {
            uint32_t off = SWZ128((uint32_t)((nbase + jb * 16 + nrowoff) * 128 + bkoff));
            ldsm4(bh[jb], bHi + off);
            ldsm4(bl[jb], bLo + off);
        }
        #pragma unroll
        for (int jb = 0; jb < NT; jb++)
            #pragma unroll
            for (int m = 0; m < 2; m++) {
                mma16816(acc[m * 2 * NT + jb * 2],     ah[m], bh[jb][0], bh[jb][1]);
                mma16816(acc[m * 2 * NT + jb * 2 + 1], ah[m], bh[jb][2], bh[jb][3]);
            }
        #pragma unroll
        for (int jb = 0; jb < NT; jb++)
            #pragma unroll
            for (int m = 0; m < 2; m++) {
                mma16816(acc[m * 2 * NT + jb * 2],     al[m], bh[jb][0], bh[jb][1]);
                mma16816(acc[m * 2 * NT + jb * 2 + 1], al[m], bh[jb][2], bh[jb][3]);
            }
        #pragma unroll
        for (int jb = 0; jb < NT; jb++)
            #pragma unroll
            for (int m = 0; m < 2; m++) {
                mma16816(acc[m * 2 * NT + jb * 2],     ah[m], bl[jb][0], bl[jb][1]);
                mma16816(acc[m * 2 * NT + jb * 2 + 1], ah[m], bl[jb][2], bl[jb][3]);
            }
    }
}

// ---------------------------------------------------------------------------
// fp16 2-pass warp MMA over one K-chunk of 64 (recurrence):
// gates += (h_hi + h_lo) @ W_f16^T. W single-precision-level fp16.
// ---------------------------------------------------------------------------
__device__ __forceinline__ void warp_mma_chunk2(
    uint32_t aHi, uint32_t aLo, uint32_t bW,
    int mrow, int nbase, int lane, float acc[][4])
{
    const int arowoff = (lane & 7) + ((lane >> 3) & 1) * 8;
    const int nrowoff = (lane & 7) + ((lane >> 4) & 1) * 8;
    #pragma unroll
    for (int kk = 0; kk < 4; kk++) {
        uint32_t ah[2][4], al[2][4], bw[4];
        const int akoff = kk * 32 + (lane >> 4) * 16;
        const int bkoff = kk * 32 + ((lane >> 3) & 1) * 16;
        #pragma unroll
        for (int m = 0; m < 2; m++) {
            uint32_t off = SWZ128((uint32_t)((mrow + m * 16 + arowoff) * 128 + akoff));
            ldsm4(ah[m], aHi + off);
            ldsm4(al[m], aLo + off);
        }
        {
            uint32_t off = SWZ128((uint32_t)((nbase + nrowoff) * 128 + bkoff));
            ldsm4(bw, bW + off);
        }
        #pragma unroll
        for (int m = 0; m < 2; m++) {
            mma16816h(acc[m * 2],     ah[m], bw[0], bw[1]);
            mma16816h(acc[m * 2 + 1], ah[m], bw[2], bw[3]);
        }
        #pragma unroll
        for (int m = 0; m < 2; m++) {
            mma16816h(acc[m * 2],     al[m], bw[0], bw[1]);
            mma16816h(acc[m * 2 + 1], al[m], bw[2], bw[3]);
        }
    }
}

// ---------------------------------------------------------------------------
// Prep kernels (device symbols bound in device code — R3 lesson).
// ---------------------------------------------------------------------------
__global__ void split_kernel(const float* __restrict__ src, int which, size_t n) {
    size_t stride = (size_t)gridDim.x * blockDim.x;
    if (which == 2) {   // Whh -> single fp16
        for (size_t i = (size_t)blockIdx.x * blockDim.x + threadIdx.x; i < n; i += stride)
            g_Whh_f16[i] = __float2half(src[i]);
        return;
    }
    __nv_bfloat16* hi = (which == 0) ? g_x_hi : g_Wih_hi;
    __nv_bfloat16* lo = (which == 0) ? g_x_lo : g_Wih_lo;
    for (size_t i = (size_t)blockIdx.x * blockDim.x + threadIdx.x; i < n; i += stride) {
        float v = src[i];
        __nv_bfloat16 h = __float2bfloat16(v);
        hi[i] = h;
        lo[i] = __float2bfloat16(v - __bfloat162float(h));
    }
}

__global__ void init_state_kernel() {
    int i = blockIdx.x * blockDim.x + threadIdx.x;
    if (i == 0) g_bar = 0u;
    if (i < Bv * Hv) {
        g_h_hi[0][i] = __float2half(0.0f);
        g_h_lo[0][i] = __float2half(0.0f);
        g_c[i] = 0.0f;
    }
}

// ---------------------------------------------------------------------------
// Input GEMM (bf16 HMMA 3-pass, unchanged from R4-R7 pass)
// ---------------------------------------------------------------------------
#define G_STAGE 65536
#define G_SMEM  (2 * G_STAGE)

__device__ __forceinline__ void gemm_load(uint32_t sb, int s, int k0,
                                          int m0, int n0, int tid) {
    uint32_t base = sb + (uint32_t)s * G_STAGE;
    #pragma unroll
    for (int r = 0; r < 8; r++) {
        int idx = tid + r * 256;
        int hf = idx >> 10, rem = idx & 1023;
        int row = rem >> 3, c = rem & 7;
        const __nv_bfloat16* src = (hf ? g_x_lo : g_x_hi)
                                   + (size_t)(m0 + row) * Iv + k0 + c * 8;
        cp16(base + hf * 16384 + SWZ128((uint32_t)(row * 128 + c * 16)), src);
    }
    #pragma unroll
    for (int r = 0; r < 8; r++) {
        int idx = tid + r * 256;
        int hf = idx >> 10, rem = idx & 1023;
        int row = rem >> 3, c = rem & 7;
        const __nv_bfloat16* src = (hf ? g_Wih_lo : g_Wih_hi)
                                   + (size_t)(n0 + row) * Iv + k0 + c * 8;
        cp16(base + 32768 + hf * 16384 + SWZ128((uint32_t)(row * 128 + c * 16)), src);
    }
}

__global__ void __launch_bounds__(256, 1) gemm_in_mma(const float* __restrict__ bias)
{
    extern __shared__ char smem[];
    uint32_t sb = smem_u32(smem);
    const int tid = threadIdx.x, lane = tid & 31, wid = tid >> 5;
    const int m0 = blockIdx.y * 128, n0 = blockIdx.x * 128;

    float acc[16][4];
    #pragma unroll
    for (int i = 0; i < 16; i++)
        #pragma unroll
        for (int j = 0; j < 4; j++) acc[i][j] = 0.0f;

    gemm_load(sb, 0, 0, m0, n0, tid);
    CP_COMMIT();

    const int mrow = (wid & 3) * 32, nbase = (wid >> 2) * 64;
    for (int it = 0; it < 16; it++) {
        const int s = it & 1;
        if (it + 1 < 16) {
            gemm_load(sb, (it + 1) & 1, (it + 1) * 64, m0, n0, tid);
            CP_COMMIT();
            CP_WAIT(1);
        } else {
            CP_WAIT(0);
        }
        __syncthreads();
        uint32_t base = sb + (uint32_t)s * G_STAGE;
        warp_mma_chunk<4>(base, base + 16384, base + 32768, base + 49152,
                          mrow, nbase, lane, acc);
        __syncthreads();
    }

    #pragma unroll
    for (int m = 0; m < 2; m++)
        #pragma unroll
        for (int j = 0; j < 8; j++) {
            float* a = acc[m * 8 + j];
            int gr = m0 + (wid & 3) * 32 + m * 16 + (lane >> 2);
            int n  = n0 + (wid >> 2) * 64 + j * 8 + 2 * (lane & 3);
            float b0 = bias[n], b1 = bias[n + 1];
            int bi0 = gr >> 9, tt0 = gr & 511;
            float* o0 = g_Gx + ((size_t)tt0 * Bv + bi0) * Gv + n;
            o0[0] = a[0] + b0; o0[1] = a[1] + b1;
            int gr2 = gr + 8, bi2 = gr2 >> 9, tt2 = gr2 & 511;
            float* o2 = g_Gx + ((size_t)tt2 * Bv + bi2) * Gv + n;
            o2[0] = a[2] + b0; o2[1] = a[3] + b1;
        }
}

// ---------------------------------------------------------------------------
// Persistent LSTM recurrence (fp16 2-pass). 128 CTAs x 256 threads, 1 CTA/SM.
// CTA owns 8 hidden cols (32 gate rows). W_f16 (64KB) SMEM-resident.
// Per step: 16 K-chunks of 64, 3-stage cp.async pipeline, one __syncthreads
// per chunk; Gx slice prefetched to SMEM; single global barrier per step.
// ---------------------------------------------------------------------------
#define WS    0                            /* 16 chunks x 4KB = 64KB */
#define AB    65536                        /* 3 stages x (hi 8KB + lo 8KB) */
#define GXS   (AB + 3 * 16384)             /* 114688: 64 x 144B = 9216 */
#define GS0   (GXS + 9216)                 /* 123904: 64 x 33 fp32 = 8448 */
#define GS1   (GS0 + 8448)                 /* 132352 */
#define P_SMEM (GS1 + 8448)                /* 140800 */

__device__ __forceinline__ void persist_loadA(uint32_t sb, int st, int k0,
                                              const __half* __restrict__ hHi,
                                              const __half* __restrict__ hLo,
                                              int tid) {
    uint32_t base = sb + AB + (uint32_t)st * 16384;
    #pragma unroll
    for (int r = 0; r < 4; r++) {          // 1024 cp16 = 16KB
        int idx = tid + r * 256;
        int hf = idx >> 9, rem = idx & 511;
        int row = rem >> 3, c = rem & 7;   // row = batch 0..63
        const __half* src = (hf ? hLo : hHi) + (size_t)row * Hv + k0 + c * 8;
        cp16(base + hf * 8192 + SWZ128((uint32_t)(row * 128 + c * 16)), src);
    }
}

__global__ void __launch_bounds__(256, 1) lstm_persistent(float* __restrict__ dout)
{
    extern __shared__ char smem[];
    uint32_t sb = smem_u32(smem);
    const int tid = threadIdx.x, lane = tid & 31, wid = tid >> 5;
    const int j0 = blockIdx.x * 8;
    const int par = wid >> 2;                  // chunk parity this warp computes
    const int mrow = (wid & 1) * 32;
    const int nbase = ((wid >> 1) & 1) * 16;

    // ---- Preload W_f16 tile: 32 gate rows x K=1024 = 64KB, chunk-major
    #pragma unroll
    for (int r = 0; r < 16; r++) {             // 4096 cp16
        int idx = tid + r * 256;
        int chunk = idx >> 8, within = idx & 255;
        int row = within >> 3, c = within & 7;
        int gate = row >> 3, jc = row & 7;
        const __half* src = g_Whh_f16
            + (size_t)(gate * Hv + j0 + jc) * Hv + chunk * 64 + c * 8;
        cp16(sb + WS + chunk * 4096 + SWZ128((uint32_t)(row * 128 + c * 16)), src);
    }
    CP_COMMIT();
    CP_WAIT(0);
    __syncthreads();

    float* Gs0 = (float*)(smem + GS0);
    float* Gs1 = (float*)(smem + GS1);
    float* gxs = (float*)(smem + GXS);

    for (int t = 0; t < Tv; t++) {
        const __half* hHi = g_h_hi[t & 1];
        const __half* hLo = g_h_lo[t & 1];
        __half* hHiN = g_h_hi[(t + 1) & 1];
        __half* hLoN = g_h_lo[(t + 1) & 1];

        float acc[4][4];
        #pragma unroll
        for (int i = 0; i < 4; i++)
            #pragma unroll
            for (int j = 0; j < 4; j++) acc[i][j] = 0.0f;

        // prologue: chunk 0 (+ Gx gate-slice prefetch), chunk 1
        persist_loadA(sb, 0, 0, hHi, hLo, tid);
        {
            const float* gxbase = g_Gx + ((size_t)t * Bv) * Gv + j0;
            #pragma unroll
            for (int r = 0; r < 2; r++) {       // 512 cp16 = 8KB
                int idx = tid + r * 256;
                int b = idx >> 3;
                int gate = (idx >> 1) & 3, hf = idx & 1;
                cp16(sb + GXS + (uint32_t)(b * 144 + gate * 32 + hf * 16),
                     gxbase + (size_t)b * Gv + gate * Hv + hf * 4);
            }
        }
        CP_COMMIT();
        persist_loadA(sb, 1, 64, hHi, hLo, tid);
        CP_COMMIT();

        for (int it = 0; it < 16; it++) {
            if (it == 15) { CP_WAIT(0); } else { CP_WAIT(1); }
            __syncthreads();
            if ((it & 1) == par) {
                uint32_t aHi = sb + AB + (uint32_t)(it % 3) * 16384;
                warp_mma_chunk2(aHi, aHi + 8192,
                                sb + WS + (uint32_t)it * 4096,
                                mrow, nbase, lane, acc);
            }
            if (it + 2 < 16) {
                persist_loadA(sb, (it + 2) % 3, (it + 2) * 64, hHi, hLo, tid);
                CP_COMMIT();
            }
        }

        // Stage partial gates (per k-parity buffer)
        float* Gs = par ? Gs1 : Gs0;
        #pragma unroll
        for (int m = 0; m < 2; m++)
            #pragma unroll
            for (int p = 0; p < 2; p++) {
                float* a = acc[m * 2 + p];
                int r0 = mrow + m * 16 + (lane >> 2);
                int cc = nbase + p * 8 + 2 * (lane & 3);
                Gs[r0 * 33 + cc]           = a[0];
                Gs[r0 * 33 + cc + 1]       = a[1];
                Gs[(r0 + 8) * 33 + cc]     = a[2];
                Gs[(r0 + 8) * 33 + cc + 1] = a[3];
            }
        __syncthreads();

        // Fused cell update: 512 cells (64 batch x 8 hidden cols)
        #pragma unroll
        for (int p = 0; p < 2; p++) {
            int cell = tid + p * 256;
            int b = cell >> 3, jc = cell & 7;
            const float* gx = gxs + b * 36;
            float gi = Gs0[b * 33 + jc]      + Gs1[b * 33 + jc]      + gx[jc];
            float gf = Gs0[b * 33 + 8 + jc]  + Gs1[b * 33 + 8 + jc]  + gx[8 + jc];
            float gg = Gs0[b * 33 + 16 + jc] + Gs1[b * 33 + 16 + jc] + gx[16 + jc];
            float go = Gs0[b * 33 + 24 + jc] + Gs1[b * 33 + 24 + jc] + gx[24 + jc];

            int hidx = b * Hv + j0 + jc;
            float c_old = g_c[hidx];
            float cn = sigm(gf) * c_old + sigm(gi) * tanh_fast(gg);
            float hn = sigm(go) * tanh_fast(cn);
            g_c[hidx] = cn;

            __half hi = __float2half(hn);
            hHiN[hidx] = hi;
            hLoN[hidx] = __float2half(hn - __half2float(hi));

            dout[(size_t)b * Tv * Hv + (size_t)t * Hv + j0 + jc] = hn;
            if (t == Tv - 1) {
                size_t obase = (size_t)Bv * Tv * Hv;
                dout[obase + hidx] = hn;                    // h_T
                dout[obase + (size_t)Bv * Hv + hidx] = cn;  // c_T
            }
        }

        // ---- Global barrier (release-arrive by tid0, acquire-spin, fanout)
        __syncthreads();
        if (tid == 0) {
            unsigned int ignored;
            asm volatile("atom.add.release.gpu.u32 %0, [%1], 1;"
                         : "=r"(ignored) : "l"(&g_bar) : "memory");
            unsigned int target = 128u * (unsigned int)(t + 1);
            unsigned int cur;
            do {
                asm volatile("ld.acquire.gpu.u32 %0, [%1];"
                             : "=r"(cur) : "l"(&g_bar) : "memory");
                if (cur >= target) break;
                asm volatile("nanosleep.u32 16;");
            } while (true);
        }
        __syncthreads();
    }
}

// ---------------------------------------------------------------------------
// Launch
// ---------------------------------------------------------------------------
extern "C" void kernel_launch(void* const* d_in, const int* in_sizes, int n_in,
                              void* d_out, int out_size)
{
    const float* x    = (const float*)d_in[0];  // [B, T, I]
    const float* Wih  = (const float*)d_in[1];  // [4H, I]
    const float* Whh  = (const float*)d_in[2];  // [4H, H]
    const float* bias = (const float*)d_in[3];  // [4H]
    float* out = (float*)d_out;
    (void)in_sizes; (void)n_in; (void)out_size;

    cudaFuncSetAttribute(gemm_in_mma,     cudaFuncAttributeMaxDynamicSharedMemorySize, G_SMEM);
    cudaFuncSetAttribute(lstm_persistent, cudaFuncAttributeMaxDynamicSharedMemorySize, P_SMEM);

    split_kernel<<<8192, 256>>>(x,   0, (size_t)Bv * Tv * Iv);
    split_kernel<<<4096, 256>>>(Wih, 1, (size_t)Gv * Iv);
    split_kernel<<<4096, 256>>>(Whh, 2, (size_t)Gv * Hv);
    init_state_kernel<<<(Bv * Hv + 255) / 256, 256>>>();

    dim3 ggrid(Gv / 128, (Bv * Tv) / 128);   // (32, 256)
    gemm_in_mma<<<ggrid, 256, G_SMEM>>>(bias);

    lstm_persistent<<<128, 256, P_SMEM>>>(out);
}

// round 9
// speedup vs baseline: 1.5403x; 1.2631x over previous
#include <cuda_runtime.h>
#include <cuda_bf16.h>
#include <cuda_fp16.h>
#include <cstdint>
#include <math.h>

#define Bv 64
#define Tv 512
#define Iv 1024
#define Hv 1024
#define Gv 4096   // 4*H

// ---------------------------------------------------------------------------
// Static device scratch
// ---------------------------------------------------------------------------
__device__ float g_Gx[(size_t)Tv * Bv * Gv];              // 512MB [T][B][4H]
__device__ __nv_bfloat16 g_x_hi[(size_t)Bv * Tv * Iv];    // 64MB
__device__ __nv_bfloat16 g_x_lo[(size_t)Bv * Tv * Iv];    // 64MB
__device__ __nv_bfloat16 g_Wih_hi[(size_t)Gv * Iv];       // 8MB
__device__ __nv_bfloat16 g_Wih_lo[(size_t)Gv * Iv];
__device__ __half g_Whh_f16[(size_t)Gv * Hv];             // 8MB, single fp16
__device__ __half g_h[2][Bv * Hv];                        // fp16 h (single)
__device__ float g_c[Bv * Hv];
__device__ unsigned int g_bar;

// ---------------------------------------------------------------------------
// Helpers
// ---------------------------------------------------------------------------
__device__ __forceinline__ uint32_t smem_u32(const void* p) {
    uint32_t a;
    asm("{ .reg .u64 t; cvta.to.shared.u64 t, %1; cvt.u32.u64 %0, t; }"
        : "=r"(a) : "l"(p));
    return a;
}

#define SWZ128(o) ((o) ^ (((o) >> 3) & 0x70))

__device__ __forceinline__ void cp16(uint32_t dst, const void* src) {
    asm volatile("cp.async.cg.shared.global [%0], [%1], 16;" :: "r"(dst), "l"(src));
}
#define CP_COMMIT() asm volatile("cp.async.commit_group;" ::: "memory")
#define CP_WAIT(n)  asm volatile("cp.async.wait_group %0;" :: "n"(n) : "memory")

__device__ __forceinline__ void ldsm4(uint32_t* r, uint32_t addr) {
    asm volatile("ldmatrix.sync.aligned.m8n8.x4.shared.b16 {%0,%1,%2,%3}, [%4];"
        : "=r"(r[0]), "=r"(r[1]), "=r"(r[2]), "=r"(r[3]) : "r"(addr));
}

__device__ __forceinline__ void mma16816(float* d, const uint32_t* a,
                                         uint32_t b0, uint32_t b1) {
    asm volatile(
        "mma.sync.aligned.m16n8k16.row.col.f32.bf16.bf16.f32 "
        "{%0,%1,%2,%3}, {%4,%5,%6,%7}, {%8,%9}, {%0,%1,%2,%3};"
        : "+f"(d[0]), "+f"(d[1]), "+f"(d[2]), "+f"(d[3])
        : "r"(a[0]), "r"(a[1]), "r"(a[2]), "r"(a[3]), "r"(b0), "r"(b1));
}

__device__ __forceinline__ void mma16816h(float* d, const uint32_t* a,
                                          uint32_t b0, uint32_t b1) {
    asm volatile(
        "mma.sync.aligned.m16n8k16.row.col.f32.f16.f16.f32 "
        "{%0,%1,%2,%3}, {%4,%5,%6,%7}, {%8,%9}, {%0,%1,%2,%3};"
        : "+f"(d[0]), "+f"(d[1]), "+f"(d[2]), "+f"(d[3])
        : "r"(a[0]), "r"(a[1]), "r"(a[2]), "r"(a[3]), "r"(b0), "r"(b1));
}

__device__ __forceinline__ float sigm(float x) {
    return 1.0f / (1.0f + __expf(-x));
}
__device__ __forceinline__ float tanh_fast(float x) {
    float cx = fminf(fmaxf(x, -10.0f), 10.0f);
    float e = __expf(2.0f * cx);
    return (e - 1.0f) / (e + 1.0f);
}

// ---------------------------------------------------------------------------
// bf16 3-pass warp MMA over one K-chunk of 64 (input GEMM, proven R4-R8).
// ---------------------------------------------------------------------------
template <int NT>
__device__ __forceinline__ void warp_mma_chunk(
    uint32_t aHi, uint32_t aLo, uint32_t bHi, uint32_t bLo,
    int mrow, int nbase, int lane, float acc[][4])
{
    const int arowoff = (lane & 7) + ((lane >> 3) & 1) * 8;
    const int nrowoff = (lane & 7) + ((lane >> 4) & 1) * 8;
    #pragma unroll
    for (int kk = 0; kk < 4; kk++) {
        uint32_t ah[2][4], al[2][4], bh[NT][4], bl[NT][4];
        const int akoff = kk * 32 + (lane >> 4) * 16;
        const int bkoff = kk * 32 + ((lane >> 3) & 1) * 16;
        #pragma unroll
        for (int m = 0; m < 2; m++) {
            uint32_t off = SWZ128((uint32_t)((mrow + m * 16 + arowoff) * 128 + akoff));
            ldsm4(ah[m], aHi + off);
            ldsm4(al[m], aLo + off);
        }
        #pragma unroll
        for (int jb = 0; jb < NT; jb++) {
            uint32_t off = SWZ128((uint32_t)((nbase + jb * 16 + nrowoff) * 128 + bkoff));
            ldsm4(bh[jb], bHi + off);
            ldsm4(bl[jb], bLo + off);
        }
        #pragma unroll
        for (int jb = 0; jb < NT; jb++)
            #pragma unroll
            for (int m = 0; m < 2; m++) {
                mma16816(acc[m * 2 * NT + jb * 2],     ah[m], bh[jb][0], bh[jb][1]);
                mma16816(acc[m * 2 * NT + jb * 2 + 1], ah[m], bh[jb][2], bh[jb][3]);
            }
        #pragma unroll
        for (int jb = 0; jb < NT; jb++)
            #pragma unroll
            for (int m = 0; m < 2; m++) {
                mma16816(acc[m * 2 * NT + jb * 2],     al[m], bh[jb][0], bh[jb][1]);
                mma16816(acc[m * 2 * NT + jb * 2 + 1], al[m], bh[jb][2], bh[jb][3]);
            }
        #pragma unroll
        for (int jb = 0; jb < NT; jb++)
            #pragma unroll
            for (int m = 0; m < 2; m++) {
                mma16816(acc[m * 2 * NT + jb * 2],     ah[m], bl[jb][0], bl[jb][1]);
                mma16816(acc[m * 2 * NT + jb * 2 + 1], ah[m], bl[jb][2], bl[jb][3]);
            }
    }
}

// ---------------------------------------------------------------------------
// fp16 SINGLE-pass warp MMA over one 64-wide K sub-tile (recurrence).
// gates += h_f16 @ W_f16^T.
// ---------------------------------------------------------------------------
__device__ __forceinline__ void warp_mma_1p(
    uint32_t aT, uint32_t bW, int mrow, int nbase, int lane, float acc[][4])
{
    const int arowoff = (lane & 7) + ((lane >> 3) & 1) * 8;
    const int nrowoff = (lane & 7) + ((lane >> 4) & 1) * 8;
    #pragma unroll
    for (int kk = 0; kk < 4; kk++) {
        uint32_t ah[2][4], bw[4];
        const int akoff = kk * 32 + (lane >> 4) * 16;
        const int bkoff = kk * 32 + ((lane >> 3) & 1) * 16;
        #pragma unroll
        for (int m = 0; m < 2; m++) {
            uint32_t off = SWZ128((uint32_t)((mrow + m * 16 + arowoff) * 128 + akoff));
            ldsm4(ah[m], aT + off);
        }
        {
            uint32_t off = SWZ128((uint32_t)((nbase + nrowoff) * 128 + bkoff));
            ldsm4(bw, bW + off);
        }
        #pragma unroll
        for (int m = 0; m < 2; m++) {
            mma16816h(acc[m * 2],     ah[m], bw[0], bw[1]);
            mma16816h(acc[m * 2 + 1], ah[m], bw[2], bw[3]);
        }
    }
}

// ---------------------------------------------------------------------------
// Prep kernels (device symbols bound in device code — R3 lesson).
// ---------------------------------------------------------------------------
__global__ void split_kernel(const float* __restrict__ src, int which, size_t n) {
    size_t stride = (size_t)gridDim.x * blockDim.x;
    if (which == 2) {   // Whh -> single fp16
        for (size_t i = (size_t)blockIdx.x * blockDim.x + threadIdx.x; i < n; i += stride)
            g_Whh_f16[i] = __float2half(src[i]);
        return;
    }
    __nv_bfloat16* hi = (which == 0) ? g_x_hi : g_Wih_hi;
    __nv_bfloat16* lo = (which == 0) ? g_x_lo : g_Wih_lo;
    for (size_t i = (size_t)blockIdx.x * blockDim.x + threadIdx.x; i < n; i += stride) {
        float v = src[i];
        __nv_bfloat16 h = __float2bfloat16(v);
        hi[i] = h;
        lo[i] = __float2bfloat16(v - __bfloat162float(h));
    }
}

__global__ void init_state_kernel() {
    int i = blockIdx.x * blockDim.x + threadIdx.x;
    if (i == 0) g_bar = 0u;
    if (i < Bv * Hv) {
        g_h[0][i] = __float2half(0.0f);
        g_c[i] = 0.0f;
    }
}

// ---------------------------------------------------------------------------
// Input GEMM (bf16 HMMA 3-pass, unchanged from R4-R8 pass)
// ---------------------------------------------------------------------------
#define G_STAGE 65536
#define G_SMEM  (2 * G_STAGE)

__device__ __forceinline__ void gemm_load(uint32_t sb, int s, int k0,
                                          int m0, int n0, int tid) {
    uint32_t base = sb + (uint32_t)s * G_STAGE;
    #pragma unroll
    for (int r = 0; r < 8; r++) {
        int idx = tid + r * 256;
        int hf = idx >> 10, rem = idx & 1023;
        int row = rem >> 3, c = rem & 7;
        const __nv_bfloat16* src = (hf ? g_x_lo : g_x_hi)
                                   + (size_t)(m0 + row) * Iv + k0 + c * 8;
        cp16(base + hf * 16384 + SWZ128((uint32_t)(row * 128 + c * 16)), src);
    }
    #pragma unroll
    for (int r = 0; r < 8; r++) {
        int idx = tid + r * 256;
        int hf = idx >> 10, rem = idx & 1023;
        int row = rem >> 3, c = rem & 7;
        const __nv_bfloat16* src = (hf ? g_Wih_lo : g_Wih_hi)
                                   + (size_t)(n0 + row) * Iv + k0 + c * 8;
        cp16(base + 32768 + hf * 16384 + SWZ128((uint32_t)(row * 128 + c * 16)), src);
    }
}

__global__ void __launch_bounds__(256, 1) gemm_in_mma(const float* __restrict__ bias)
{
    extern __shared__ char smem[];
    uint32_t sb = smem_u32(smem);
    const int tid = threadIdx.x, lane = tid & 31, wid = tid >> 5;
    const int m0 = blockIdx.y * 128, n0 = blockIdx.x * 128;

    float acc[16][4];
    #pragma unroll
    for (int i = 0; i < 16; i++)
        #pragma unroll
        for (int j = 0; j < 4; j++) acc[i][j] = 0.0f;

    gemm_load(sb, 0, 0, m0, n0, tid);
    CP_COMMIT();

    const int mrow = (wid & 3) * 32, nbase = (wid >> 2) * 64;
    for (int it = 0; it < 16; it++) {
        const int s = it & 1;
        if (it + 1 < 16) {
            gemm_load(sb, (it + 1) & 1, (it + 1) * 64, m0, n0, tid);
            CP_COMMIT();
            CP_WAIT(1);
        } else {
            CP_WAIT(0);
        }
        __syncthreads();
        uint32_t base = sb + (uint32_t)s * G_STAGE;
        warp_mma_chunk<4>(base, base + 16384, base + 32768, base + 49152,
                          mrow, nbase, lane, acc);
        __syncthreads();
    }

    #pragma unroll
    for (int m = 0; m < 2; m++)
        #pragma unroll
        for (int j = 0; j < 8; j++) {
            float* a = acc[m * 8 + j];
            int gr = m0 + (wid & 3) * 32 + m * 16 + (lane >> 2);
            int n  = n0 + (wid >> 2) * 64 + j * 8 + 2 * (lane & 3);
            float b0 = bias[n], b1 = bias[n + 1];
            int bi0 = gr >> 9, tt0 = gr & 511;
            float* o0 = g_Gx + ((size_t)tt0 * Bv + bi0) * Gv + n;
            o0[0] = a[0] + b0; o0[1] = a[1] + b1;
            int gr2 = gr + 8, bi2 = gr2 >> 9, tt2 = gr2 & 511;
            float* o2 = g_Gx + ((size_t)tt2 * Bv + bi2) * Gv + n;
            o2[0] = a[2] + b0; o2[1] = a[3] + b1;
        }
}

// ---------------------------------------------------------------------------
// Persistent LSTM recurrence (fp16 single-pass). 128 CTAs x 256 threads.
// CTA owns 8 hidden cols (32 gate rows). W_f16 (64KB) SMEM-resident.
// Per step: 8 K-chunks of 128 (two 64-wide sub-tiles each), 3-stage cp.async
// pipeline, one __syncthreads per chunk; Gx slice prefetched; single global
// barrier per step.
// ---------------------------------------------------------------------------
#define WS    0                            /* 16 sub-chunks x 4KB = 64KB */
#define AB    65536                        /* 3 stages x 16KB A tiles */
#define GXS   (AB + 3 * 16384)             /* 114688: 64 x 144B = 9216 */
#define GS0   (GXS + 9216)                 /* 123904: 64 x 33 fp32 = 8448 */
#define GS1   (GS0 + 8448)                 /* 132352 */
#define P_SMEM (GS1 + 8448)                /* 140800 */

// Load A tile for K-chunk of 128 (two 64-wide sub-tiles, 16KB total).
__device__ __forceinline__ void persist_loadA(uint32_t sb, int st, int k0,
                                              const __half* __restrict__ hIn,
                                              int tid) {
    uint32_t base = sb + AB + (uint32_t)st * 16384;
    #pragma unroll
    for (int r = 0; r < 4; r++) {          // 1024 cp16 = 16KB
        int idx = tid + r * 256;
        int sub = idx >> 9, rem = idx & 511;
        int row = rem >> 3, c = rem & 7;   // row = batch 0..63
        const __half* src = hIn + (size_t)row * Hv + k0 + sub * 64 + c * 8;
        cp16(base + sub * 8192 + SWZ128((uint32_t)(row * 128 + c * 16)), src);
    }
}

__global__ void __launch_bounds__(256, 1) lstm_persistent(float* __restrict__ dout)
{
    extern __shared__ char smem[];
    uint32_t sb = smem_u32(smem);
    const int tid = threadIdx.x, lane = tid & 31, wid = tid >> 5;
    const int j0 = blockIdx.x * 8;
    const int par = wid >> 2;                  // chunk parity this warp computes
    const int mrow = (wid & 1) * 32;
    const int nbase = ((wid >> 1) & 1) * 16;

    // ---- Preload W_f16 tile: 32 gate rows x K=1024 = 64KB, sub-chunk-major
    #pragma unroll
    for (int r = 0; r < 16; r++) {             // 4096 cp16
        int idx = tid + r * 256;
        int chunk = idx >> 8, within = idx & 255;
        int row = within >> 3, c = within & 7;
        int gate = row >> 3, jc = row & 7;
        const __half* src = g_Whh_f16
            + (size_t)(gate * Hv + j0 + jc) * Hv + chunk * 64 + c * 8;
        cp16(sb + WS + chunk * 4096 + SWZ128((uint32_t)(row * 128 + c * 16)), src);
    }
    CP_COMMIT();
    CP_WAIT(0);
    __syncthreads();

    float* Gs0 = (float*)(smem + GS0);
    float* Gs1 = (float*)(smem + GS1);
    float* gxs = (float*)(smem + GXS);

    for (int t = 0; t < Tv; t++) {
        const __half* hIn = g_h[t & 1];
        __half* hOut      = g_h[(t + 1) & 1];

        float acc[4][4];
        #pragma unroll
        for (int i = 0; i < 4; i++)
            #pragma unroll
            for (int j = 0; j < 4; j++) acc[i][j] = 0.0f;

        // prologue: chunk 0 (+ Gx gate-slice prefetch), chunk 1
        persist_loadA(sb, 0, 0, hIn, tid);
        {
            const float* gxbase = g_Gx + ((size_t)t * Bv) * Gv + j0;
            #pragma unroll
            for (int r = 0; r < 2; r++) {       // 512 cp16 = 8KB
                int idx = tid + r * 256;
                int b = idx >> 3;
                int gate = (idx >> 1) & 3, hf = idx & 1;
                cp16(sb + GXS + (uint32_t)(b * 144 + gate * 32 + hf * 16),
                     gxbase + (size_t)b * Gv + gate * Hv + hf * 4);
            }
        }
        CP_COMMIT();
        persist_loadA(sb, 1, 128, hIn, tid);
        CP_COMMIT();

        for (int it = 0; it < 8; it++) {
            if (it == 7) { CP_WAIT(0); } else { CP_WAIT(1); }
            __syncthreads();
            if ((it & 1) == par) {
                uint32_t aT = sb + AB + (uint32_t)(it % 3) * 16384;
                warp_mma_1p(aT,        sb + WS + (uint32_t)(2 * it) * 4096,
                            mrow, nbase, lane, acc);
                warp_mma_1p(aT + 8192, sb + WS + (uint32_t)(2 * it + 1) * 4096,
                            mrow, nbase, lane, acc);
            }
            if (it + 2 < 8) {
                persist_loadA(sb, (it + 2) % 3, (it + 2) * 128, hIn, tid);
                CP_COMMIT();
            }
        }

        // Stage partial gates (per k-parity buffer)
        float* Gs = par ? Gs1 : Gs0;
        #pragma unroll
        for (int m = 0; m < 2; m++)
            #pragma unroll
            for (int p = 0; p < 2; p++) {
                float* a = acc[m * 2 + p];
                int r0 = mrow + m * 16 + (lane >> 2);
                int cc = nbase + p * 8 + 2 * (lane & 3);
                Gs[r0 * 33 + cc]           = a[0];
                Gs[r0 * 33 + cc + 1]       = a[1];
                Gs[(r0 + 8) * 33 + cc]     = a[2];
                Gs[(r0 + 8) * 33 + cc + 1] = a[3];
            }
        __syncthreads();

        // Fused cell update: 512 cells (64 batch x 8 hidden cols)
        #pragma unroll
        for (int p = 0; p < 2; p++) {
            int cell = tid + p * 256;
            int b = cell >> 3, jc = cell & 7;
            const float* gx = gxs + b * 36;
            float gi = Gs0[b * 33 + jc]      + Gs1[b * 33 + jc]      + gx[jc];
            float gf = Gs0[b * 33 + 8 + jc]  + Gs1[b * 33 + 8 + jc]  + gx[8 + jc];
            float gg = Gs0[b * 33 + 16 + jc] + Gs1[b * 33 + 16 + jc] + gx[16 + jc];
            float go = Gs0[b * 33 + 24 + jc] + Gs1[b * 33 + 24 + jc] + gx[24 + jc];

            int hidx = b * Hv + j0 + jc;
            float c_old = g_c[hidx];
            float cn = sigm(gf) * c_old + sigm(gi) * tanh_fast(gg);
            float hn = sigm(go) * tanh_fast(cn);
            g_c[hidx] = cn;

            hOut[hidx] = __float2half(hn);

            dout[(size_t)b * Tv * Hv + (size_t)t * Hv + j0 + jc] = hn;
            if (t == Tv - 1) {
                size_t obase = (size_t)Bv * Tv * Hv;
                dout[obase + hidx] = hn;                    // h_T
                dout[obase + (size_t)Bv * Hv + hidx] = cn;  // c_T
            }
        }

        // ---- Global barrier (release-arrive by tid0, acquire-spin, fanout)
        __syncthreads();
        if (tid == 0) {
            unsigned int ignored;
            asm volatile("atom.add.release.gpu.u32 %0, [%1], 1;"
                         : "=r"(ignored) : "l"(&g_bar) : "memory");
            unsigned int target = 128u * (unsigned int)(t + 1);
            unsigned int cur;
            do {
                asm volatile("ld.acquire.gpu.u32 %0, [%1];"
                             : "=r"(cur) : "l"(&g_bar) : "memory");
                if (cur >= target) break;
                asm volatile("nanosleep.u32 16;");
            } while (true);
        }
        __syncthreads();
    }
}

// ---------------------------------------------------------------------------
// Launch
// ---------------------------------------------------------------------------
extern "C" void kernel_launch(void* const* d_in, const int* in_sizes, int n_in,
                              void* d_out, int out_size)
{
    const float* x    = (const float*)d_in[0];  // [B, T, I]
    const float* Wih  = (const float*)d_in[1];  // [4H, I]
    const float* Whh  = (const float*)d_in[2];  // [4H, H]
    const float* bias = (const float*)d_in[3];  // [4H]
    float* out = (float*)d_out;
    (void)in_sizes; (void)n_in; (void)out_size;

    cudaFuncSetAttribute(gemm_in_mma,     cudaFuncAttributeMaxDynamicSharedMemorySize, G_SMEM);
    cudaFuncSetAttribute(lstm_persistent, cudaFuncAttributeMaxDynamicSharedMemorySize, P_SMEM);

    split_kernel<<<8192, 256>>>(x,   0, (size_t)Bv * Tv * Iv);
    split_kernel<<<4096, 256>>>(Wih, 1, (size_t)Gv * Iv);
    split_kernel<<<4096, 256>>>(Whh, 2, (size_t)Gv * Hv);
    init_state_kernel<<<(Bv * Hv + 255) / 256, 256>>>();

    dim3 ggrid(Gv / 128, (Bv * Tv) / 128);   // (32, 256)
    gemm_in_mma<<<ggrid, 256, G_SMEM>>>(bias);

    lstm_persistent<<<128, 256, P_SMEM>>>(out);
}